// round 11
// baseline (speedup 1.0000x reference)
#include <cuda_runtime.h>
#include <math.h>
#include <float.h>

#define B_   128
#define H_   512
#define E_   256
#define ND_  128
#define V_   5000
#define K0_  384      // E_ + ND_

typedef unsigned long long u64;

// ---------------- persistent device state ----------------
__device__ __align__(16) float g_h0T[2][H_ * B_];   // [k][b], ping-pong
__device__ __align__(16) float g_h1T[2][H_ * B_];
__device__ __align__(16) float g_c0[H_ * B_];       // cell state [j][b]
__device__ __align__(16) float g_c1[H_ * B_];
__device__ __align__(16) float g_xnT[ND_ * B_];     // noise transposed [k][b]
__device__ __align__(16) float g_cval[125 * B_];    // [p][b]
__device__ int   g_cidx[125 * B_];

__device__ __forceinline__ float sigmf(float x) { return 1.0f / (1.0f + expf(-x)); }

__device__ __forceinline__ u64 dup2(float a) {
    u64 r; asm("mov.b64 %0,{%1,%1};" : "=l"(r) : "f"(a)); return r;
}
__device__ __forceinline__ u64 pack2(float lo, float hi) {
    u64 r; asm("mov.b64 %0,{%1,%2};" : "=l"(r) : "f"(lo), "f"(hi)); return r;
}
__device__ __forceinline__ void fma2(u64& d, u64 x, u64 w) {
    asm("fma.rn.f32x2 %0,%1,%2,%0;" : "+l"(d) : "l"(x), "l"(w));
}
__device__ __forceinline__ void unpack2(u64 a, float& x, float& y) {
    asm("mov.b64 {%0,%1},%2;" : "=f"(x), "=f"(y) : "l"(a));
}

// ================= init =================
__global__ void k_init(const float* __restrict__ noise) {
    int i = blockIdx.x * 256 + threadIdx.x;
    if (i < H_ * B_) {
        g_h0T[0][i] = 0.f; g_h1T[0][i] = 0.f;
        g_c0[i] = 0.f;     g_c1[i] = 0.f;
    }
    if (i < ND_ * B_) {
        int k = i >> 7, b = i & 127;
        g_xnT[k * B_ + b] = noise[b * ND_ + k];
    }
}

// ---- stage 16 rows x 128 k of weights, duplicated as (w,w) u64 pairs ----
// rows: r = g*4 + jj  ->  global row (g*H_ + jbase + jj)
__device__ __forceinline__ void stage16(
    const float* __restrict__ Wsrc, int jbase, int KIH, int kbase,
    int tid, u64 (*wsm)[128])
{
    #pragma unroll
    for (int i = 0; i < 2; i++) {
        int idx = tid + i * 256;          // 0..511 (512 float4 = 16 rows * 32)
        int row = idx >> 5;               // 0..15
        int kq  = (idx & 31) * 4;         // 0..124
        int g = row >> 2, jj = row & 3;
        float4 w = *(const float4*)(Wsrc + (size_t)(g * H_ + jbase + jj) * KIH + kbase + kq);
        ulonglong2* d = (ulonglong2*)&wsm[row][kq];
        d[0] = make_ulonglong2(dup2(w.x), dup2(w.y));
        d[1] = make_ulonglong2(dup2(w.z), dup2(w.w));
    }
}

// ---- compute one 128-k chunk, x from global [k][B_] layout ----
__device__ __forceinline__ void comp_chunk_g(
    const float* __restrict__ xk, int b2, int rg, u64 acc[4], u64 (*wsm)[128])
{
    #pragma unroll 4
    for (int kc = 0; kc < 128; kc += 4) {
        u64 x0 = *(const u64*)(xk + (size_t)(kc + 0) * B_ + b2);
        u64 x1 = *(const u64*)(xk + (size_t)(kc + 1) * B_ + b2);
        u64 x2 = *(const u64*)(xk + (size_t)(kc + 2) * B_ + b2);
        u64 x3 = *(const u64*)(xk + (size_t)(kc + 3) * B_ + b2);
        #pragma unroll
        for (int g = 0; g < 4; g++) {
            ulonglong2 wA = *(const ulonglong2*)&wsm[g * 4 + rg][kc];
            ulonglong2 wB = *(const ulonglong2*)&wsm[g * 4 + rg][kc + 2];
            fma2(acc[g], x0, wA.x); fma2(acc[g], x1, wA.y);
            fma2(acc[g], x2, wB.x); fma2(acc[g], x3, wB.y);
        }
    }
}

// ---- compute one 128-k chunk, x gathered from two embedding rows ----
__device__ __forceinline__ void comp_chunk_emb(
    const float* __restrict__ e0, const float* __restrict__ e1,
    int rg, u64 acc[4], u64 (*wsm)[128])
{
    #pragma unroll 4
    for (int kc = 0; kc < 128; kc += 4) {
        float4 f0 = *(const float4*)(e0 + kc);
        float4 f1 = *(const float4*)(e1 + kc);
        u64 x0 = pack2(f0.x, f1.x);
        u64 x1 = pack2(f0.y, f1.y);
        u64 x2 = pack2(f0.z, f1.z);
        u64 x3 = pack2(f0.w, f1.w);
        #pragma unroll
        for (int g = 0; g < 4; g++) {
            ulonglong2 wA = *(const ulonglong2*)&wsm[g * 4 + rg][kc];
            ulonglong2 wB = *(const ulonglong2*)&wsm[g * 4 + rg][kc + 2];
            fma2(acc[g], x0, wA.x); fma2(acc[g], x1, wA.y);
            fma2(acc[g], x2, wB.x); fma2(acc[g], x3, wB.y);
        }
    }
}

// ================= LSTM kernels =================
// grid 128, block 256 = 8 warps: rg = wid>>1 (j within block), bg = wid&1 (batch half).
// Warp tile: 4 gate-rows (all gates of j = jbase+rg) x 64 batch. Lane owns b-pair.
template<int LAYER>
__global__ void __launch_bounds__(256) k_lstm(
    const float* __restrict__ emb,
    const float* __restrict__ Wih, const float* __restrict__ Whh,
    const float* __restrict__ bih, const float* __restrict__ bhh, int t)
{
    constexpr int KIH = (LAYER == 0) ? K0_ : H_;
    __shared__ __align__(16) u64 wsm[16][128];   // 16KB
    __shared__ int s_tok[B_];

    const int tid = threadIdx.x, bid = blockIdx.x;
    const int lane = tid & 31, wid = tid >> 5;
    const int rg = wid >> 1, bg = wid & 1;
    const int b2 = bg * 64 + lane * 2;
    const int jbase = bid * 4;

    const float* h_rd = (LAYER == 0) ? g_h0T[t & 1] : g_h1T[t & 1];
    float*       h_wr = (LAYER == 0) ? g_h0T[(t + 1) & 1] : g_h1T[(t + 1) & 1];
    float*       cst  = (LAYER == 0) ? g_c0 : g_c1;

    // ---- fused token reduce (layer 0) ----
    if (LAYER == 0) {
        if (tid < B_) {
            int tok = 1;
            if (t > 0) {
                float bv = -FLT_MAX; int bi = 0x7fffffff;
                #pragma unroll 5
                for (int p = 0; p < 125; p++) {
                    float v = g_cval[p * B_ + tid];
                    int  ix = g_cidx[p * B_ + tid];
                    if (v > bv || (v == bv && ix < bi)) { bv = v; bi = ix; }
                }
                tok = bi;
            }
            s_tok[tid] = tok;
        }
        __syncthreads();
    }

    u64 acc[4] = {0ull, 0ull, 0ull, 0ull};

    // ---- segment 1: input (emb+noise for L0, h0_new for L1) ----
    #pragma unroll 1
    for (int c = 0; c < KIH / 128; c++) {
        __syncthreads();
        stage16(Wih, jbase, KIH, c * 128, tid, wsm);
        __syncthreads();
        if (LAYER == 0) {
            if (c < 2) {
                const float* e0 = emb + (size_t)s_tok[b2]     * E_ + c * 128;
                const float* e1 = emb + (size_t)s_tok[b2 + 1] * E_ + c * 128;
                comp_chunk_emb(e0, e1, rg, acc, wsm);
            } else {
                comp_chunk_g(g_xnT, b2, rg, acc, wsm);      // c==2 -> noise k 0..127
            }
        } else {
            comp_chunk_g(g_h0T[(t + 1) & 1] + (size_t)c * 128 * B_, b2, rg, acc, wsm);
        }
    }
    // ---- segment 2: recurrent ----
    #pragma unroll 1
    for (int c = 0; c < 4; c++) {
        __syncthreads();
        stage16(Whh, jbase, H_, c * 128, tid, wsm);
        __syncthreads();
        comp_chunk_g(h_rd + (size_t)c * 128 * B_, b2, rg, acc, wsm);
    }

    // ---- warp-local epilogue: j = jbase+rg, batch b2,b2+1 ----
    {
        int j = jbase + rg;
        float gx[4], gy[4];
        #pragma unroll
        for (int g = 0; g < 4; g++) {
            float bs = bih[g * H_ + j] + bhh[g * H_ + j];
            unpack2(acc[g], gx[g], gy[g]);
            gx[g] += bs; gy[g] += bs;
        }
        float2 cold = *(float2*)&cst[j * B_ + b2];
        float i0 = sigmf(gx[0]), f0 = sigmf(gx[1]), g0 = tanhf(gx[2]), o0 = sigmf(gx[3]);
        float i1 = sigmf(gy[0]), f1 = sigmf(gy[1]), g1 = tanhf(gy[2]), o1 = sigmf(gy[3]);
        float c0n = f0 * cold.x + i0 * g0;
        float c1n = f1 * cold.y + i1 * g1;
        *(float2*)&cst[j * B_ + b2]  = make_float2(c0n, c1n);
        *(float2*)&h_wr[j * B_ + b2] = make_float2(o0 * tanhf(c0n), o1 * tanhf(c1n));
    }
}

// ================= logits + partial argmax =================
// grid 125, block 256 = 8 warps: rg = wid>>1 (10 vocab rows each), bg = wid&1.
__global__ void __launch_bounds__(256) k_logits(
    const float* __restrict__ Wout, const float* __restrict__ bout,
    float* __restrict__ out, int t, int T)
{
    __shared__ __align__(16) u64 wsm[40][128];   // 40KB
    __shared__ float s_cv[4][B_];
    __shared__ int   s_ci[4][B_];

    const int tid = threadIdx.x, bid = blockIdx.x;
    const int lane = tid & 31, wid = tid >> 5;
    const int rg = wid >> 1, bg = wid & 1;
    const int b2 = bg * 64 + lane * 2;
    const int vb = bid * 40;

    const float* h1 = g_h1T[(t + 1) & 1];

    u64 acc[10];
    #pragma unroll
    for (int a = 0; a < 10; a++) acc[a] = 0ull;

    #pragma unroll 1
    for (int c = 0; c < 4; c++) {
        __syncthreads();
        // stage 40 rows x 128 k (1280 float4, 5 per thread)
        #pragma unroll
        for (int i = 0; i < 5; i++) {
            int idx = tid + i * 256;
            int row = idx >> 5;
            int kq  = (idx & 31) * 4;
            float4 w = *(const float4*)(Wout + (size_t)(vb + row) * H_ + c * 128 + kq);
            ulonglong2* d = (ulonglong2*)&wsm[row][kq];
            d[0] = make_ulonglong2(dup2(w.x), dup2(w.y));
            d[1] = make_ulonglong2(dup2(w.z), dup2(w.w));
        }
        __syncthreads();
        const float* xk = h1 + (size_t)c * 128 * B_;
        #pragma unroll 2
        for (int kc = 0; kc < 128; kc += 4) {
            u64 x0 = *(const u64*)(xk + (size_t)(kc + 0) * B_ + b2);
            u64 x1 = *(const u64*)(xk + (size_t)(kc + 1) * B_ + b2);
            u64 x2 = *(const u64*)(xk + (size_t)(kc + 2) * B_ + b2);
            u64 x3 = *(const u64*)(xk + (size_t)(kc + 3) * B_ + b2);
            #pragma unroll
            for (int q = 0; q < 10; q++) {
                ulonglong2 wA = *(const ulonglong2*)&wsm[rg * 10 + q][kc];
                ulonglong2 wB = *(const ulonglong2*)&wsm[rg * 10 + q][kc + 2];
                fma2(acc[q], x0, wA.x); fma2(acc[q], x1, wA.y);
                fma2(acc[q], x2, wB.x); fma2(acc[q], x3, wB.y);
            }
        }
    }

    // ---- epilogue: bias, write, per-lane argmax over 10 rows x 2 b ----
    {
        float vx[10], vy[10];
        #pragma unroll
        for (int q = 0; q < 10; q++) {
            float bq = bout[vb + rg * 10 + q];
            unpack2(acc[q], vx[q], vy[q]);
            vx[q] += bq; vy[q] += bq;
        }
        float* op0 = out + ((size_t)(b2 + 0) * T + t) * V_ + vb + rg * 10;
        float* op1 = out + ((size_t)(b2 + 1) * T + t) * V_ + vb + rg * 10;
        float bv0 = -FLT_MAX, bv1 = -FLT_MAX; int bi0 = 0, bi1 = 0;
        #pragma unroll
        for (int q = 0; q < 10; q++) {
            op0[q] = vx[q];
            op1[q] = vy[q];
            int col = vb + rg * 10 + q;
            if (vx[q] > bv0) { bv0 = vx[q]; bi0 = col; }   // first max on ties
            if (vy[q] > bv1) { bv1 = vy[q]; bi1 = col; }
        }
        s_cv[rg][b2]     = bv0;  s_ci[rg][b2]     = bi0;
        s_cv[rg][b2 + 1] = bv1;  s_ci[rg][b2 + 1] = bi1;
    }
    __syncthreads();
    if (tid < B_) {
        int b = tid;
        float bv = -FLT_MAX; int bi = 0x7fffffff;
        #pragma unroll
        for (int p = 0; p < 4; p++) {
            float v = s_cv[p][b]; int ix = s_ci[p][b];
            if (v > bv || (v == bv && ix < bi)) { bv = v; bi = ix; }
        }
        g_cval[bid * B_ + b] = bv;
        g_cidx[bid * B_ + b] = bi;
    }
}

// ================= final heads =================
__global__ void k_head(const float* __restrict__ Watt, const float* __restrict__ batt,
                       const float* __restrict__ Wsoph, const float* __restrict__ bsoph,
                       float* __restrict__ out, int T)
{
    const float* h1 = g_h1T[T & 1];
    int m = blockIdx.x;          // 0..23
    int b = threadIdx.x;         // 0..127
    size_t base = (size_t)B_ * T * V_;
    const float* w; float bias; float* op;
    if (m < 8) {
        w = Watt + m * H_; bias = batt[m];
        op = out + base + (size_t)b * 8 + m;
    } else {
        int mm = m - 8;
        w = Wsoph + mm * H_; bias = bsoph[mm];
        op = out + base + (size_t)B_ * 8 + (size_t)b * 16 + mm;
    }
    float a = 0.f;
    #pragma unroll 4
    for (int k = 0; k < H_; k += 4) {
        float4 wv = *(const float4*)(w + k);
        a += h1[(k + 0) * B_ + b] * wv.x + h1[(k + 1) * B_ + b] * wv.y
           + h1[(k + 2) * B_ + b] * wv.z + h1[(k + 3) * B_ + b] * wv.w;
    }
    *op = a + bias;
}

// ================= launch =================
extern "C" void kernel_launch(void* const* d_in, const int* in_sizes, int n_in,
                              void* d_out, int out_size)
{
    const float* noise = (const float*)d_in[0];
    const float* emb   = (const float*)d_in[1];
    const float* Wih0  = (const float*)d_in[2];
    const float* Whh0  = (const float*)d_in[3];
    const float* bih0  = (const float*)d_in[4];
    const float* bhh0  = (const float*)d_in[5];
    const float* Wih1  = (const float*)d_in[6];
    const float* Whh1  = (const float*)d_in[7];
    const float* bih1  = (const float*)d_in[8];
    const float* bhh1  = (const float*)d_in[9];
    const float* Wout  = (const float*)d_in[10];
    const float* bout  = (const float*)d_in[11];
    const float* Watt  = (const float*)d_in[12];
    const float* batt  = (const float*)d_in[13];
    const float* Wsoph = (const float*)d_in[14];
    const float* bsoph = (const float*)d_in[15];
    float* out = (float*)d_out;

    int T = (out_size - B_ * 24) / (B_ * V_);
    if (T <= 0) T = 200;

    k_init<<<256, 256>>>(noise);
    for (int t = 0; t < T; t++) {
        k_lstm<0><<<128, 256>>>(emb, Wih0, Whh0, bih0, bhh0, t);
        k_lstm<1><<<128, 256>>>(emb, Wih1, Whh1, bih1, bhh1, t);
        k_logits<<<125, 256>>>(Wout, bout, out, t, T);
    }
    k_head<<<24, 128>>>(Watt, batt, Wsoph, bsoph, out, T);
}